// round 8
// baseline (speedup 1.0000x reference)
#include <cuda_runtime.h>
#include <cuda_bf16.h>
#include <cuda_fp16.h>
#include <math.h>

#define SEQ   4096
#define NHEAD 8
#define DHEAD 64

__device__ __half g_qkv_h[1536 * SEQ];   // [3*512][4096] d-major, Q pre-scaled
__device__ __half g_att_h[512 * SEQ];    // [512][4096]   d-major

__device__ __forceinline__ float ex2(float x) {
    float r; asm("ex2.approx.f32 %0, %1;" : "=f"(r) : "f"(x)); return r;
}
__device__ __forceinline__ unsigned pack_h2(float lo, float hi) {
    unsigned d;
    asm("cvt.rn.f16x2.f32 %0, %1, %2;" : "=r"(d) : "f"(hi), "f"(lo));
    return d;
}

__device__ __forceinline__ void mma_f16(float4& d, const unsigned* a,
                                        unsigned b0, unsigned b1) {
    asm volatile(
        "mma.sync.aligned.m16n8k16.row.col.f32.f16.f16.f32 "
        "{%0,%1,%2,%3}, {%4,%5,%6,%7}, {%8,%9}, {%0,%1,%2,%3};"
        : "+f"(d.x), "+f"(d.y), "+f"(d.z), "+f"(d.w)
        : "r"(a[0]), "r"(a[1]), "r"(a[2]), "r"(a[3]), "r"(b0), "r"(b1));
}
__device__ __forceinline__ void ldsm_x4(unsigned& r0, unsigned& r1,
                                        unsigned& r2, unsigned& r3, unsigned addr) {
    asm volatile("ldmatrix.sync.aligned.m8n8.x4.shared.b16 {%0,%1,%2,%3}, [%4];"
                 : "=r"(r0), "=r"(r1), "=r"(r2), "=r"(r3) : "r"(addr));
}
__device__ __forceinline__ void ldsm_x4_trans(unsigned& r0, unsigned& r1,
                                              unsigned& r2, unsigned& r3, unsigned addr) {
    asm volatile("ldmatrix.sync.aligned.m8n8.x4.trans.shared.b16 {%0,%1,%2,%3}, [%4];"
                 : "=r"(r0), "=r"(r1), "=r"(r2), "=r"(r3) : "r"(addr));
}

// ---------------------------------------------------------------------------
// fp16 tensor-core GEMM: C[M,N] = A[M,K](fp32) * B[K,N] (+bias), row-major.
// CTA 128x128, 8 warps, warp tile 32x64, BK=32 (2 k16 chunks).
// B_HALF: B is fp16 (else fp32, converted). C_HALF: C is fp16; rows < scaleRows
// are multiplied by scaleQ before store (Q pre-scaling). Else C fp32 + bias.
// ---------------------------------------------------------------------------
#define AP 40    // As pitch (halves): 80B = 20 banks/row -> ldmatrix conflict-free
#define BP 136   // Bs pitch (halves): 272B = 4 banks/row -> ldmatrix conflict-free

template<bool B_HALF, bool C_HALF>
__global__ void __launch_bounds__(256) gemm_f16(
    const float* __restrict__ A, const void* __restrict__ Bv,
    const float* __restrict__ bias, void* __restrict__ Cv,
    int M, int N, int K, float scaleQ, int scaleRows)
{
    __shared__ __align__(16) __half As[128 * AP];
    __shared__ __align__(16) __half Bs[32 * BP];

    const int tid  = threadIdx.x;
    const int lane = tid & 31;
    const int w    = tid >> 5;
    const int g    = lane >> 2;
    const int t    = lane & 3;
    const int mb   = (w >> 1) * 32;
    const int nb   = (w & 1) * 64;
    const int m0   = blockIdx.y * 128, n0 = blockIdx.x * 128;

    const unsigned as_base = (unsigned)__cvta_generic_to_shared(As);
    const unsigned bs_base = (unsigned)__cvta_generic_to_shared(Bs);

    float4 acc[2][8];
    #pragma unroll
    for (int mt = 0; mt < 2; mt++)
        #pragma unroll
        for (int nj = 0; nj < 8; nj++) acc[mt][nj] = make_float4(0.f, 0.f, 0.f, 0.f);

    for (int k0 = 0; k0 < K; k0 += 32) {
        // Stage A (128x32 fp32 -> half)
        float4 av[4];
        int ar[4], ak[4];
        #pragma unroll
        for (int u = 0; u < 4; u++) {
            int s = tid + u * 256;
            ar[u] = s >> 3; ak[u] = (s & 7) * 4;
            av[u] = *(const float4*)(A + (size_t)(m0 + ar[u]) * K + k0 + ak[u]);
        }
        // Stage B
        uint4  bh[2];
        float4 bf[4];
        int bk[4], bn[4];
        if (B_HALF) {
            const __half* Bh = (const __half*)Bv;
            #pragma unroll
            for (int u = 0; u < 2; u++) {
                int s = tid + u * 256;
                bk[u] = s >> 4; bn[u] = (s & 15) * 8;
                bh[u] = *(const uint4*)(Bh + (size_t)(k0 + bk[u]) * N + n0 + bn[u]);
            }
        } else {
            const float* Bf = (const float*)Bv;
            #pragma unroll
            for (int u = 0; u < 4; u++) {
                int s = tid + u * 256;
                bk[u] = s >> 5; bn[u] = (s & 31) * 4;
                bf[u] = *(const float4*)(Bf + (size_t)(k0 + bk[u]) * N + n0 + bn[u]);
            }
        }
        __syncthreads();
        #pragma unroll
        for (int u = 0; u < 4; u++) {
            uint2 ap;
            ap.x = pack_h2(av[u].x, av[u].y);
            ap.y = pack_h2(av[u].z, av[u].w);
            *(uint2*)&As[ar[u] * AP + ak[u]] = ap;
        }
        if (B_HALF) {
            #pragma unroll
            for (int u = 0; u < 2; u++)
                *(uint4*)&Bs[bk[u] * BP + bn[u]] = bh[u];
        } else {
            #pragma unroll
            for (int u = 0; u < 4; u++) {
                uint2 bp;
                bp.x = pack_h2(bf[u].x, bf[u].y);
                bp.y = pack_h2(bf[u].z, bf[u].w);
                *(uint2*)&Bs[bk[u] * BP + bn[u]] = bp;
            }
        }
        __syncthreads();

        #pragma unroll
        for (int kc = 0; kc < 2; kc++) {
            unsigned af[2][4];
            #pragma unroll
            for (int mt = 0; mt < 2; mt++) {
                unsigned addr = as_base +
                    ((mb + mt * 16 + (lane & 15)) * AP + 16 * kc + 8 * (lane >> 4)) * 2;
                ldsm_x4(af[mt][0], af[mt][1], af[mt][2], af[mt][3], addr);
            }
            #pragma unroll
            for (int njp = 0; njp < 4; njp++) {
                unsigned b0, b1, b2, b3;
                unsigned addr = bs_base +
                    ((16 * kc + (lane & 15)) * BP + nb + 8 * (2 * njp + (lane >> 4))) * 2;
                ldsm_x4_trans(b0, b1, b2, b3, addr);
                mma_f16(acc[0][2 * njp    ], af[0], b0, b1);
                mma_f16(acc[1][2 * njp    ], af[1], b0, b1);
                mma_f16(acc[0][2 * njp + 1], af[0], b2, b3);
                mma_f16(acc[1][2 * njp + 1], af[1], b2, b3);
            }
        }
        __syncthreads();
    }

    #pragma unroll
    for (int mt = 0; mt < 2; mt++) {
        int r0 = m0 + mb + mt * 16 + g;
        int r1 = r0 + 8;
        if (C_HALF) {
            __half* Ch = (__half*)Cv;
            float sc0 = (r0 < scaleRows) ? scaleQ : 1.0f;
            float sc1 = (r1 < scaleRows) ? scaleQ : 1.0f;
            #pragma unroll
            for (int nj = 0; nj < 8; nj++) {
                int col = n0 + nb + 8 * nj + 2 * t;
                unsigned lo = pack_h2(acc[mt][nj].x * sc0, acc[mt][nj].y * sc0);
                unsigned hi = pack_h2(acc[mt][nj].z * sc1, acc[mt][nj].w * sc1);
                *(unsigned*)((__half*)Ch + (size_t)r0 * N + col) = lo;
                *(unsigned*)((__half*)Ch + (size_t)r1 * N + col) = hi;
            }
        } else {
            float* Cf = (float*)Cv;
            float bb0 = bias ? bias[r0] : 0.0f;
            float bb1 = bias ? bias[r1] : 0.0f;
            #pragma unroll
            for (int nj = 0; nj < 8; nj++) {
                int col = n0 + nb + 8 * nj + 2 * t;
                float2 lo = {acc[mt][nj].x + bb0, acc[mt][nj].y + bb0};
                float2 hi = {acc[mt][nj].z + bb1, acc[mt][nj].w + bb1};
                *(float2*)(Cf + (size_t)r0 * N + col) = lo;
                *(float2*)(Cf + (size_t)r1 * N + col) = hi;
            }
        }
    }
}

// ---------------------------------------------------------------------------
// Flash attention, fp16 m16n8k16, fp32 accumulate. Inputs/outputs fp16.
// CTA = (head, 128 rows), 4 warps, warp = 32 i-rows; j-tile 64; 2 CTAs/SM.
// Q pre-scaled by 0.125*log2(e) in the QKV GEMM. Output half -> g_att_h.
// ---------------------------------------------------------------------------
#define KPH 72

__global__ void __launch_bounds__(128, 2) flash_fp16_kernel()
{
    __shared__ __align__(16) __half Ks[64 * KPH];
    __shared__ __align__(16) __half Vs[64 * KPH];

    const int tid  = threadIdx.x;
    const int lane = tid & 31;
    const int w    = tid >> 5;
    const int g    = lane >> 2;
    const int t    = lane & 3;
    const int h    = blockIdx.y;
    const int iBase = blockIdx.x * 128 + w * 32;

    const __half* qp = g_qkv_h + (size_t)(h * 64) * SEQ;
    const __half* kp = g_qkv_h + (size_t)(512 + h * 64) * SEQ;
    const __half* vp = g_qkv_h + (size_t)(1024 + h * 64) * SEQ;

    const unsigned ks_base = (unsigned)__cvta_generic_to_shared(Ks);
    const unsigned vs_base = (unsigned)__cvta_generic_to_shared(Vs);

    // Q A-fragments: pre-scaled halves straight from global.
    unsigned qf[2][4][4];
    #pragma unroll
    for (int mt = 0; mt < 2; mt++) {
        int I = iBase + mt * 16;
        #pragma unroll
        for (int kc = 0; kc < 4; kc++) {
            int d0 = 16 * kc + 2 * t;
            #pragma unroll
            for (int r = 0; r < 4; r++) {
                int dv = d0 + (r >> 1) * 8;
                int iv = I + g + (r & 1) * 8;
                __half2 hh = __halves2half2(qp[(size_t)dv * SEQ + iv],
                                            qp[(size_t)(dv + 1) * SEQ + iv]);
                qf[mt][kc][r] = *(unsigned*)&hh;
            }
        }
    }

    float4 ob[2][8];
    #pragma unroll
    for (int mt = 0; mt < 2; mt++)
        #pragma unroll
        for (int nd = 0; nd < 8; nd++) ob[mt][nd] = make_float4(0.f, 0.f, 0.f, 0.f);
    float mrow[2][2], lrow[2][2];
    #pragma unroll
    for (int mt = 0; mt < 2; mt++) {
        mrow[mt][0] = -1e30f; mrow[mt][1] = -1e30f;
        lrow[mt][0] = 0.f;    lrow[mt][1] = 0.f;
    }

    const int kRow = lane & 15;
    const int kColSel = lane >> 4;
    const int vRow = lane & 7;
    const int vTileSel = lane >> 4;
    const int vColSel = (lane >> 3) & 1;

    for (int jt = 0; jt < 64; jt++) {
        const int j0 = jt * 64;

        // Stage K/V tiles: straight uint4 half copies (no conversion).
        uint4 kv4[4], vv4[4];
        int dd[4], jj[4];
        #pragma unroll
        for (int u = 0; u < 4; u++) {
            int s = tid + u * 128;
            dd[u] = s >> 3;
            jj[u] = (s & 7) * 8;
            kv4[u] = *(const uint4*)(kp + (size_t)dd[u] * SEQ + j0 + jj[u]);
            vv4[u] = *(const uint4*)(vp + (size_t)dd[u] * SEQ + j0 + jj[u]);
        }
        __syncthreads();
        #pragma unroll
        for (int u = 0; u < 4; u++) {
            *(uint4*)&Ks[dd[u] * KPH + jj[u]] = kv4[u];
            *(uint4*)&Vs[dd[u] * KPH + jj[u]] = vv4[u];
        }
        __syncthreads();

        // ---- S = Q K^T ----
        float4 sb[2][8];
        #pragma unroll
        for (int mt = 0; mt < 2; mt++)
            #pragma unroll
            for (int nj = 0; nj < 8; nj++) sb[mt][nj] = make_float4(0.f, 0.f, 0.f, 0.f);

        #pragma unroll
        for (int kc = 0; kc < 4; kc++) {
            #pragma unroll
            for (int njp = 0; njp < 4; njp++) {
                unsigned b0, b1, b2, b3;
                unsigned addr = ks_base +
                    ((16 * kc + kRow) * KPH + 8 * (2 * njp + kColSel)) * 2;
                ldsm_x4_trans(b0, b1, b2, b3, addr);
                mma_f16(sb[0][2 * njp    ], qf[0][kc], b0, b1);
                mma_f16(sb[1][2 * njp    ], qf[1][kc], b0, b1);
                mma_f16(sb[0][2 * njp + 1], qf[0][kc], b2, b3);
                mma_f16(sb[1][2 * njp + 1], qf[1][kc], b2, b3);
            }
        }

        // ---- online softmax (log2 domain) ----
        unsigned pf[2][4][4];
        #pragma unroll
        for (int mt = 0; mt < 2; mt++) {
            float mx0 = -1e30f, mx1 = -1e30f;
            #pragma unroll
            for (int nj = 0; nj < 8; nj++) {
                mx0 = fmaxf(mx0, fmaxf(sb[mt][nj].x, sb[mt][nj].y));
                mx1 = fmaxf(mx1, fmaxf(sb[mt][nj].z, sb[mt][nj].w));
            }
            mx0 = fmaxf(mx0, __shfl_xor_sync(0xffffffffu, mx0, 1));
            mx0 = fmaxf(mx0, __shfl_xor_sync(0xffffffffu, mx0, 2));
            mx1 = fmaxf(mx1, __shfl_xor_sync(0xffffffffu, mx1, 1));
            mx1 = fmaxf(mx1, __shfl_xor_sync(0xffffffffu, mx1, 2));

            float mn0 = fmaxf(mrow[mt][0], mx0);
            float mn1 = fmaxf(mrow[mt][1], mx1);
            float al0 = ex2(mrow[mt][0] - mn0);
            float al1 = ex2(mrow[mt][1] - mn1);
            mrow[mt][0] = mn0; mrow[mt][1] = mn1;

            float rs0 = 0.f, rs1 = 0.f;
            #pragma unroll
            for (int nj = 0; nj < 8; nj++) {
                float exv = ex2(sb[mt][nj].x - mn0);
                float eyv = ex2(sb[mt][nj].y - mn0);
                float ezv = ex2(sb[mt][nj].z - mn1);
                float ewv = ex2(sb[mt][nj].w - mn1);
                rs0 += exv + eyv; rs1 += ezv + ewv;
                int kc = nj >> 1, base = (nj & 1) * 2;
                pf[mt][kc][base + 0] = pack_h2(exv, eyv);
                pf[mt][kc][base + 1] = pack_h2(ezv, ewv);
            }
            rs0 += __shfl_xor_sync(0xffffffffu, rs0, 1);
            rs0 += __shfl_xor_sync(0xffffffffu, rs0, 2);
            rs1 += __shfl_xor_sync(0xffffffffu, rs1, 1);
            rs1 += __shfl_xor_sync(0xffffffffu, rs1, 2);
            lrow[mt][0] = lrow[mt][0] * al0 + rs0;
            lrow[mt][1] = lrow[mt][1] * al1 + rs1;
            #pragma unroll
            for (int nd = 0; nd < 8; nd++) {
                ob[mt][nd].x *= al0; ob[mt][nd].y *= al0;
                ob[mt][nd].z *= al1; ob[mt][nd].w *= al1;
            }
        }

        // ---- O += P V ----
        #pragma unroll
        for (int kc = 0; kc < 4; kc++) {
            #pragma unroll
            for (int ndp = 0; ndp < 4; ndp++) {
                unsigned b0, b1, b2, b3;
                unsigned addr = vs_base +
                    ((8 * (2 * ndp + vTileSel) + vRow) * KPH
                     + 16 * kc + vColSel * 8) * 2;
                ldsm_x4(b0, b1, b2, b3, addr);
                mma_f16(ob[0][2 * ndp    ], pf[0][kc], b0, b1);
                mma_f16(ob[1][2 * ndp    ], pf[1][kc], b0, b1);
                mma_f16(ob[0][2 * ndp + 1], pf[0][kc], b2, b3);
                mma_f16(ob[1][2 * ndp + 1], pf[1][kc], b2, b3);
            }
        }
    }

    // Normalize and write half output (d-major)
    __half* op = g_att_h + (size_t)(h * 64) * SEQ;
    #pragma unroll
    for (int mt = 0; mt < 2; mt++) {
        float inv0 = 1.0f / lrow[mt][0];
        float inv1 = 1.0f / lrow[mt][1];
        int I = iBase + mt * 16;
        #pragma unroll
        for (int nd = 0; nd < 8; nd++) {
            int dcol = 8 * nd + 2 * t;
            op[(size_t)(dcol    ) * SEQ + I + g    ] = __float2half(ob[mt][nd].x * inv0);
            op[(size_t)(dcol + 1) * SEQ + I + g    ] = __float2half(ob[mt][nd].y * inv0);
            op[(size_t)(dcol    ) * SEQ + I + g + 8] = __float2half(ob[mt][nd].z * inv1);
            op[(size_t)(dcol + 1) * SEQ + I + g + 8] = __float2half(ob[mt][nd].w * inv1);
        }
    }
}

// ---------------------------------------------------------------------------
extern "C" void kernel_launch(void* const* d_in, const int* in_sizes, int n_in,
                              void* d_out, int out_size)
{
    const float* x     = (const float*)d_in[0];
    const float* w_qkv = (const float*)d_in[1];
    const float* w_out = (const float*)d_in[2];
    const float* b_out = (const float*)d_in[3];
    float* out = (float*)d_out;

    __half* qkv_ptr = nullptr;
    __half* att_ptr = nullptr;
    cudaGetSymbolAddress((void**)&qkv_ptr, g_qkv_h);
    cudaGetSymbolAddress((void**)&att_ptr, g_att_h);

    const float qscale = 0.125f * 1.44269504088896340736f;  // 1/8 * log2(e)

    // 1) QKV projection -> fp16 scratch, Q rows pre-scaled
    gemm_f16<false, true><<<dim3(4096 / 128, 1536 / 128), 256>>>(
        w_qkv, x, nullptr, qkv_ptr, 1536, SEQ, 256, qscale, 512);

    // 2) Flash attention (fp16 in/out)
    flash_fp16_kernel<<<dim3(32, NHEAD), 128>>>();

    // 3) Output projection (fp16 B) + bias -> fp32 out
    gemm_f16<true, false><<<dim3(4096 / 128, 256 / 128), 256>>>(
        w_out, att_ptr, b_out, out, 256, SEQ, 512, 1.0f, 0);
}

// round 13
// speedup vs baseline: 1.0496x; 1.0496x over previous
#include <cuda_runtime.h>
#include <cuda_bf16.h>
#include <cuda_fp16.h>
#include <math.h>

#define SEQ   4096
#define NHEAD 8
#define DHEAD 64

__device__ __align__(16) __half g_qkv_h[1536 * SEQ];  // d-major, Q pre-scaled
__device__ __align__(16) __half g_att_h[512 * SEQ];   // d-major attention output
__device__ __align__(16) __half g_x_h[256 * SEQ];     // x in fp16
__device__ __align__(16) __half g_wqkv_h[1536 * 256];
__device__ __align__(16) __half g_wout_h[256 * 512];

__device__ __forceinline__ float ex2(float x) {
    float r; asm("ex2.approx.f32 %0, %1;" : "=f"(r) : "f"(x)); return r;
}
__device__ __forceinline__ unsigned pack_h2(float lo, float hi) {
    unsigned d;
    asm("cvt.rn.f16x2.f32 %0, %1, %2;" : "=r"(d) : "f"(hi), "f"(lo));
    return d;
}
__device__ __forceinline__ void mma_f16(float4& d, const unsigned* a,
                                        unsigned b0, unsigned b1) {
    asm volatile(
        "mma.sync.aligned.m16n8k16.row.col.f32.f16.f16.f32 "
        "{%0,%1,%2,%3}, {%4,%5,%6,%7}, {%8,%9}, {%0,%1,%2,%3};"
        : "+f"(d.x), "+f"(d.y), "+f"(d.z), "+f"(d.w)
        : "r"(a[0]), "r"(a[1]), "r"(a[2]), "r"(a[3]), "r"(b0), "r"(b1));
}
__device__ __forceinline__ void ldsm_x4(unsigned& r0, unsigned& r1,
                                        unsigned& r2, unsigned& r3, unsigned addr) {
    asm volatile("ldmatrix.sync.aligned.m8n8.x4.shared.b16 {%0,%1,%2,%3}, [%4];"
                 : "=r"(r0), "=r"(r1), "=r"(r2), "=r"(r3) : "r"(addr));
}
__device__ __forceinline__ void ldsm_x4_trans(unsigned& r0, unsigned& r1,
                                              unsigned& r2, unsigned& r3, unsigned addr) {
    asm volatile("ldmatrix.sync.aligned.m8n8.x4.trans.shared.b16 {%0,%1,%2,%3}, [%4];"
                 : "=r"(r0), "=r"(r1), "=r"(r2), "=r"(r3) : "r"(addr));
}

// ---------------------------------------------------------------------------
// fp32 -> fp16 bulk convert for 3 arrays (one launch)
// ---------------------------------------------------------------------------
__global__ void __launch_bounds__(256) cvt3(
    const float* __restrict__ s0, __half* __restrict__ d0, int n0,
    const float* __restrict__ s1, __half* __restrict__ d1, int n1,
    const float* __restrict__ s2, __half* __restrict__ d2, int n2)
{
    const int q0 = n0 >> 2, q1 = n1 >> 2, q2 = n2 >> 2;
    const int total = q0 + q1 + q2;
    for (int idx = blockIdx.x * blockDim.x + threadIdx.x; idx < total;
         idx += gridDim.x * blockDim.x) {
        const float* s; __half* d; int off;
        if (idx < q0)            { s = s0; d = d0; off = idx * 4; }
        else if (idx < q0 + q1)  { s = s1; d = d1; off = (idx - q0) * 4; }
        else                     { s = s2; d = d2; off = (idx - q0 - q1) * 4; }
        float4 v = *(const float4*)(s + off);
        uint2 p;
        p.x = pack_h2(v.x, v.y);
        p.y = pack_h2(v.z, v.w);
        *(uint2*)(d + off) = p;
    }
}

// ---------------------------------------------------------------------------
// all-fp16 tensor-core GEMM, double-buffered smem.
// CTA tile (32*WM) x 128, warps in WM x 2 grid, warp tile 32x64, BK=32.
// C_HALF: fp16 out with Q pre-scaling; else fp32 + bias.
// ---------------------------------------------------------------------------
#define AP 40
#define BP 136

template<int WM, bool C_HALF>
__global__ void __launch_bounds__(WM * 64) gemm_h(
    const __half* __restrict__ A, const __half* __restrict__ B,
    const float* __restrict__ bias, void* __restrict__ Cv,
    int M, int N, int K, float scaleQ, int scaleRows)
{
    constexpr int NT = WM * 64;
    constexpr int BM = WM * 32;
    constexpr int A_LOADS = (BM * 4) / NT;   // uint4 slots per thread
    constexpr int B_LOADS = 512 / NT;

    __shared__ __align__(16) __half As[2][BM * AP];
    __shared__ __align__(16) __half Bs[2][32 * BP];

    const int tid  = threadIdx.x;
    const int lane = tid & 31;
    const int w    = tid >> 5;
    const int g    = lane >> 2;
    const int t    = lane & 3;
    const int mb   = (w >> 1) * 32;
    const int nb   = (w & 1) * 64;
    const int m0   = blockIdx.y * BM, n0 = blockIdx.x * 128;

    float4 acc[2][8];
    #pragma unroll
    for (int mt = 0; mt < 2; mt++)
        #pragma unroll
        for (int nj = 0; nj < 8; nj++) acc[mt][nj] = make_float4(0.f, 0.f, 0.f, 0.f);

    uint4 aReg[A_LOADS], bReg[B_LOADS];
    int aRow[A_LOADS], aCol[A_LOADS], bRow[B_LOADS], bCol[B_LOADS];

    #pragma unroll
    for (int u = 0; u < A_LOADS; u++) {
        int s = tid + u * NT;
        aRow[u] = s >> 2; aCol[u] = (s & 3) * 8;
    }
    #pragma unroll
    for (int u = 0; u < B_LOADS; u++) {
        int s = tid + u * NT;
        bRow[u] = s >> 4; bCol[u] = (s & 15) * 8;
    }

    // prologue: tile 0
    #pragma unroll
    for (int u = 0; u < A_LOADS; u++)
        aReg[u] = *(const uint4*)(A + (size_t)(m0 + aRow[u]) * K + aCol[u]);
    #pragma unroll
    for (int u = 0; u < B_LOADS; u++)
        bReg[u] = *(const uint4*)(B + (size_t)bRow[u] * N + n0 + bCol[u]);
    #pragma unroll
    for (int u = 0; u < A_LOADS; u++)
        *(uint4*)&As[0][aRow[u] * AP + aCol[u]] = aReg[u];
    #pragma unroll
    for (int u = 0; u < B_LOADS; u++)
        *(uint4*)&Bs[0][bRow[u] * BP + bCol[u]] = bReg[u];
    __syncthreads();

    const int NIT = K / 32;
    for (int it = 0; it < NIT; it++) {
        const int cur = it & 1;
        const unsigned as_base = (unsigned)__cvta_generic_to_shared(As[cur]);
        const unsigned bs_base = (unsigned)__cvta_generic_to_shared(Bs[cur]);

        if (it + 1 < NIT) {
            const int k0 = (it + 1) * 32;
            #pragma unroll
            for (int u = 0; u < A_LOADS; u++)
                aReg[u] = *(const uint4*)(A + (size_t)(m0 + aRow[u]) * K + k0 + aCol[u]);
            #pragma unroll
            for (int u = 0; u < B_LOADS; u++)
                bReg[u] = *(const uint4*)(B + (size_t)(k0 + bRow[u]) * N + n0 + bCol[u]);
        }

        #pragma unroll
        for (int kc = 0; kc < 2; kc++) {
            unsigned af[2][4];
            #pragma unroll
            for (int mt = 0; mt < 2; mt++) {
                unsigned addr = as_base +
                    ((mb + mt * 16 + (lane & 15)) * AP + 16 * kc + 8 * (lane >> 4)) * 2;
                ldsm_x4(af[mt][0], af[mt][1], af[mt][2], af[mt][3], addr);
            }
            #pragma unroll
            for (int njp = 0; njp < 4; njp++) {
                unsigned b0, b1, b2, b3;
                unsigned addr = bs_base +
                    ((16 * kc + (lane & 15)) * BP + nb + 8 * (2 * njp + (lane >> 4))) * 2;
                ldsm_x4_trans(b0, b1, b2, b3, addr);
                mma_f16(acc[0][2 * njp    ], af[0], b0, b1);
                mma_f16(acc[1][2 * njp    ], af[1], b0, b1);
                mma_f16(acc[0][2 * njp + 1], af[0], b2, b3);
                mma_f16(acc[1][2 * njp + 1], af[1], b2, b3);
            }
        }

        if (it + 1 < NIT) {
            const int nxt = cur ^ 1;
            #pragma unroll
            for (int u = 0; u < A_LOADS; u++)
                *(uint4*)&As[nxt][aRow[u] * AP + aCol[u]] = aReg[u];
            #pragma unroll
            for (int u = 0; u < B_LOADS; u++)
                *(uint4*)&Bs[nxt][bRow[u] * BP + bCol[u]] = bReg[u];
        }
        __syncthreads();
    }

    #pragma unroll
    for (int mt = 0; mt < 2; mt++) {
        int r0 = m0 + mb + mt * 16 + g;
        int r1 = r0 + 8;
        if (C_HALF) {
            __half* Ch = (__half*)Cv;
            float sc0 = (r0 < scaleRows) ? scaleQ : 1.0f;
            float sc1 = (r1 < scaleRows) ? scaleQ : 1.0f;
            #pragma unroll
            for (int nj = 0; nj < 8; nj++) {
                int col = n0 + nb + 8 * nj + 2 * t;
                unsigned lo = pack_h2(acc[mt][nj].x * sc0, acc[mt][nj].y * sc0);
                unsigned hi = pack_h2(acc[mt][nj].z * sc1, acc[mt][nj].w * sc1);
                *(unsigned*)(Ch + (size_t)r0 * N + col) = lo;
                *(unsigned*)(Ch + (size_t)r1 * N + col) = hi;
            }
        } else {
            float* Cf = (float*)Cv;
            float bb0 = bias ? bias[r0] : 0.0f;
            float bb1 = bias ? bias[r1] : 0.0f;
            #pragma unroll
            for (int nj = 0; nj < 8; nj++) {
                int col = n0 + nb + 8 * nj + 2 * t;
                float2 lo = {acc[mt][nj].x + bb0, acc[mt][nj].y + bb0};
                float2 hi = {acc[mt][nj].z + bb1, acc[mt][nj].w + bb1};
                *(float2*)(Cf + (size_t)r0 * N + col) = lo;
                *(float2*)(Cf + (size_t)r1 * N + col) = hi;
            }
        }
    }
}

// ---------------------------------------------------------------------------
// Flash attention, fp16 m16n8k16 (round-6 kernel, verified at 168.4us total).
// CTA = (head, 128 rows), 4 warps, warp = 32 i-rows; j-tile 64; 2 CTAs/SM.
// ---------------------------------------------------------------------------
#define KPH 72

__global__ void __launch_bounds__(128, 2) flash_fp16_kernel()
{
    __shared__ __align__(16) __half Ks[64 * KPH];
    __shared__ __align__(16) __half Vs[64 * KPH];

    const int tid  = threadIdx.x;
    const int lane = tid & 31;
    const int w    = tid >> 5;
    const int g    = lane >> 2;
    const int t    = lane & 3;
    const int h    = blockIdx.y;
    const int iBase = blockIdx.x * 128 + w * 32;

    const __half* qp = g_qkv_h + (size_t)(h * 64) * SEQ;
    const __half* kp = g_qkv_h + (size_t)(512 + h * 64) * SEQ;
    const __half* vp = g_qkv_h + (size_t)(1024 + h * 64) * SEQ;

    const unsigned ks_base = (unsigned)__cvta_generic_to_shared(Ks);
    const unsigned vs_base = (unsigned)__cvta_generic_to_shared(Vs);

    unsigned qf[2][4][4];
    #pragma unroll
    for (int mt = 0; mt < 2; mt++) {
        int I = iBase + mt * 16;
        #pragma unroll
        for (int kc = 0; kc < 4; kc++) {
            int d0 = 16 * kc + 2 * t;
            #pragma unroll
            for (int r = 0; r < 4; r++) {
                int dv = d0 + (r >> 1) * 8;
                int iv = I + g + (r & 1) * 8;
                __half2 hh = __halves2half2(qp[(size_t)dv * SEQ + iv],
                                            qp[(size_t)(dv + 1) * SEQ + iv]);
                qf[mt][kc][r] = *(unsigned*)&hh;
            }
        }
    }

    float4 ob[2][8];
    #pragma unroll
    for (int mt = 0; mt < 2; mt++)
        #pragma unroll
        for (int nd = 0; nd < 8; nd++) ob[mt][nd] = make_float4(0.f, 0.f, 0.f, 0.f);
    float mrow[2][2], lrow[2][2];
    #pragma unroll
    for (int mt = 0; mt < 2; mt++) {
        mrow[mt][0] = -1e30f; mrow[mt][1] = -1e30f;
        lrow[mt][0] = 0.f;    lrow[mt][1] = 0.f;
    }

    const int kRow = lane & 15;
    const int kColSel = lane >> 4;
    const int vRow = lane & 7;
    const int vTileSel = lane >> 4;
    const int vColSel = (lane >> 3) & 1;

    for (int jt = 0; jt < 64; jt++) {
        const int j0 = jt * 64;

        uint4 kv4[4], vv4[4];
        int dd[4], jj[4];
        #pragma unroll
        for (int u = 0; u < 4; u++) {
            int s = tid + u * 128;
            dd[u] = s >> 3;
            jj[u] = (s & 7) * 8;
            kv4[u] = *(const uint4*)(kp + (size_t)dd[u] * SEQ + j0 + jj[u]);
            vv4[u] = *(const uint4*)(vp + (size_t)dd[u] * SEQ + j0 + jj[u]);
        }
        __syncthreads();
        #pragma unroll
        for (int u = 0; u < 4; u++) {
            *(uint4*)&Ks[dd[u] * KPH + jj[u]] = kv4[u];
            *(uint4*)&Vs[dd[u] * KPH + jj[u]] = vv4[u];
        }
        __syncthreads();

        float4 sb[2][8];
        #pragma unroll
        for (int mt = 0; mt < 2; mt++)
            #pragma unroll
            for (int nj = 0; nj < 8; nj++) sb[mt][nj] = make_float4(0.f, 0.f, 0.f, 0.f);

        #pragma unroll
        for (int kc = 0; kc < 4; kc++) {
            #pragma unroll
            for (int njp = 0; njp < 4; njp++) {
                unsigned b0, b1, b2, b3;
                unsigned addr = ks_base +
                    ((16 * kc + kRow) * KPH + 8 * (2 * njp + kColSel)) * 2;
                ldsm_x4_trans(b0, b1, b2, b3, addr);
                mma_f16(sb[0][2 * njp    ], qf[0][kc], b0, b1);
                mma_f16(sb[1][2 * njp    ], qf[1][kc], b0, b1);
                mma_f16(sb[0][2 * njp + 1], qf[0][kc], b2, b3);
                mma_f16(sb[1][2 * njp + 1], qf[1][kc], b2, b3);
            }
        }

        unsigned pf[2][4][4];
        #pragma unroll
        for (int mt = 0; mt < 2; mt++) {
            float mx0 = -1e30f, mx1 = -1e30f;
            #pragma unroll
            for (int nj = 0; nj < 8; nj++) {
                mx0 = fmaxf(mx0, fmaxf(sb[mt][nj].x, sb[mt][nj].y));
                mx1 = fmaxf(mx1, fmaxf(sb[mt][nj].z, sb[mt][nj].w));
            }
            mx0 = fmaxf(mx0, __shfl_xor_sync(0xffffffffu, mx0, 1));
            mx0 = fmaxf(mx0, __shfl_xor_sync(0xffffffffu, mx0, 2));
            mx1 = fmaxf(mx1, __shfl_xor_sync(0xffffffffu, mx1, 1));
            mx1 = fmaxf(mx1, __shfl_xor_sync(0xffffffffu, mx1, 2));

            float mn0 = fmaxf(mrow[mt][0], mx0);
            float mn1 = fmaxf(mrow[mt][1], mx1);
            float al0 = ex2(mrow[mt][0] - mn0);
            float al1 = ex2(mrow[mt][1] - mn1);
            mrow[mt][0] = mn0; mrow[mt][1] = mn1;

            float rs0 = 0.f, rs1 = 0.f;
            #pragma unroll
            for (int nj = 0; nj < 8; nj++) {
                float exv = ex2(sb[mt][nj].x - mn0);
                float eyv = ex2(sb[mt][nj].y - mn0);
                float ezv = ex2(sb[mt][nj].z - mn1);
                float ewv = ex2(sb[mt][nj].w - mn1);
                rs0 += exv + eyv; rs1 += ezv + ewv;
                int kc = nj >> 1, base = (nj & 1) * 2;
                pf[mt][kc][base + 0] = pack_h2(exv, eyv);
                pf[mt][kc][base + 1] = pack_h2(ezv, ewv);
            }
            rs0 += __shfl_xor_sync(0xffffffffu, rs0, 1);
            rs0 += __shfl_xor_sync(0xffffffffu, rs0, 2);
            rs1 += __shfl_xor_sync(0xffffffffu, rs1, 1);
            rs1 += __shfl_xor_sync(0xffffffffu, rs1, 2);
            lrow[mt][0] = lrow[mt][0] * al0 + rs0;
            lrow[mt][1] = lrow[mt][1] * al1 + rs1;
            #pragma unroll
            for (int nd = 0; nd < 8; nd++) {
                ob[mt][nd].x *= al0; ob[mt][nd].y *= al0;
                ob[mt][nd].z *= al1; ob[mt][nd].w *= al1;
            }
        }

        #pragma unroll
        for (int kc = 0; kc < 4; kc++) {
            #pragma unroll
            for (int ndp = 0; ndp < 4; ndp++) {
                unsigned b0, b1, b2, b3;
                unsigned addr = vs_base +
                    ((8 * (2 * ndp + vTileSel) + vRow) * KPH
                     + 16 * kc + vColSel * 8) * 2;
                ldsm_x4(b0, b1, b2, b3, addr);
                mma_f16(ob[0][2 * ndp    ], pf[0][kc], b0, b1);
                mma_f16(ob[1][2 * ndp    ], pf[1][kc], b0, b1);
                mma_f16(ob[0][2 * ndp + 1], pf[0][kc], b2, b3);
                mma_f16(ob[1][2 * ndp + 1], pf[1][kc], b2, b3);
            }
        }
    }

    __half* op = g_att_h + (size_t)(h * 64) * SEQ;
    #pragma unroll
    for (int mt = 0; mt < 2; mt++) {
        float inv0 = 1.0f / lrow[mt][0];
        float inv1 = 1.0f / lrow[mt][1];
        int I = iBase + mt * 16;
        #pragma unroll
        for (int nd = 0; nd < 8; nd++) {
            int dcol = 8 * nd + 2 * t;
            op[(size_t)(dcol    ) * SEQ + I + g    ] = __float2half(ob[mt][nd].x * inv0);
            op[(size_t)(dcol + 1) * SEQ + I + g    ] = __float2half(ob[mt][nd].y * inv0);
            op[(size_t)(dcol    ) * SEQ + I + g + 8] = __float2half(ob[mt][nd].z * inv1);
            op[(size_t)(dcol + 1) * SEQ + I + g + 8] = __float2half(ob[mt][nd].w * inv1);
        }
    }
}

// ---------------------------------------------------------------------------
extern "C" void kernel_launch(void* const* d_in, const int* in_sizes, int n_in,
                              void* d_out, int out_size)
{
    const float* x     = (const float*)d_in[0];
    const float* w_qkv = (const float*)d_in[1];
    const float* w_out = (const float*)d_in[2];
    const float* b_out = (const float*)d_in[3];
    float* out = (float*)d_out;

    __half *qkv_ptr, *att_ptr, *x_ptr, *wqkv_ptr, *wout_ptr;
    cudaGetSymbolAddress((void**)&qkv_ptr,  g_qkv_h);
    cudaGetSymbolAddress((void**)&att_ptr,  g_att_h);
    cudaGetSymbolAddress((void**)&x_ptr,    g_x_h);
    cudaGetSymbolAddress((void**)&wqkv_ptr, g_wqkv_h);
    cudaGetSymbolAddress((void**)&wout_ptr, g_wout_h);

    const float qscale = 0.125f * 1.44269504088896340736f;  // 1/8 * log2(e)

    // 0) convert inputs to fp16
    cvt3<<<768, 256>>>(x, x_ptr, 256 * SEQ,
                       w_qkv, wqkv_ptr, 1536 * 256,
                       w_out, wout_ptr, 256 * 512);

    // 1) QKV projection -> fp16 scratch, Q rows pre-scaled (BM=128, 8 warps)
    gemm_h<4, true><<<dim3(4096 / 128, 1536 / 128), 256>>>(
        wqkv_ptr, x_ptr, nullptr, qkv_ptr, 1536, SEQ, 256, qscale, 512);

    // 2) Flash attention (fp16 in/out)
    flash_fp16_kernel<<<dim3(32, NHEAD), 128>>>();

    // 3) Output projection + bias -> fp32 out (BM=64, 4 warps, 128 CTAs)
    gemm_h<2, false><<<dim3(4096 / 128, 256 / 64), 128>>>(
        wout_ptr, att_ptr, b_out, out, 256, SEQ, 512, 1.0f, 0);
}